// round 13
// baseline (speedup 1.0000x reference)
#include <cuda_runtime.h>
#include <cstdint>

// CostVolumeLayer3D, B=2 C=64 D=32 H=64 W=64, R=2.
// out[b, ch(s,dsh), d, h, w] = (1/125) * sum_c x1[b,c,d,h,w] * x2[b,c,d-dsh,h-i_s,w-j_s]
//   s in [-4,4], dsh in [-2,2], (i_s,j_s) = (min(2,s+2), max(-2,s-2)),
//   ch = (5s+dsh) mod 125. Channels 23..102 are identically zero.
// 128-thr CTA (4 h-rows), thread = w-pair x d-pair, 90 f32x2 accumulators.
// 6-buffer cp.async pipeline, one barrier per channel PAIR, continuous 12-plane
// LDS/FMA software pipeline. NEW: odd warps process the pair in swapped channel
// order (pointer swap only) to decorrelate LDS bursts across warps.

typedef unsigned long long ull;
#define LD64(p) (*reinterpret_cast<const ull*>(p))

static __device__ __forceinline__ void cp16(uint32_t dst, const float* src, int vsz) {
    asm volatile("cp.async.cg.shared.global [%0], [%1], 16, %2;"
                 :: "r"(dst), "l"(src), "r"(vsz));
}
static __device__ __forceinline__ ull pk2(uint32_t lo, uint32_t hi) {
    ull r; asm("mov.b64 %0, {%1,%2};" : "=l"(r) : "r"(lo), "r"(hi)); return r;
}
static __device__ __forceinline__ void unpk(uint32_t& lo, uint32_t& hi, ull v) {
    asm("mov.b64 {%0,%1}, %2;" : "=r"(lo), "=r"(hi) : "l"(v));
}
static __device__ __forceinline__ void fma2(ull& acc, ull a, ull b) {
    asm("fma.rn.f32x2 %0, %1, %2, %0;" : "+l"(acc) : "l"(a), "l"(b));
}
static __device__ __forceinline__ ull mul2(ull a, ull b) {
    ull r; asm("mul.rn.f32x2 %0, %1, %2;" : "=l"(r) : "l"(a), "l"(b)); return r;
}

// Load the 7 b-values of one x2 plane from smem (pp = row gh-2, col w).
static __device__ __forceinline__ void loadp(ull t[7], const float* pp) {
    t[0] = LD64(pp - 2);    // row gh-2: cols w-2,w-1
    t[1] = LD64(pp);        //            cols w,  w+1
    t[2] = LD64(pp + 2);    //            cols w+2,w+3
    t[3] = LD64(pp + 74);   // row gh-1, cols w+2,w+3
    t[4] = LD64(pp + 146);  // row gh
    t[5] = LD64(pp + 218);  // row gh+1
    t[6] = LD64(pp + 290);  // row gh+2
}

static __device__ __forceinline__ void planefma(
    const ull t[7], int p, ull A0, ull A1, ull acc[2][5][9])
{
    uint32_t f0lo, f0hi, f2lo, f2hi, f4lo, f4hi;
    unpk(f0lo, f0hi, t[0]); unpk(f2lo, f2hi, t[1]); unpk(f4lo, f4hi, t[2]);
    ull bb[9];
    bb[0] = t[6];               // s=-4
    bb[1] = t[5];               // s=-3
    bb[2] = t[4];               // s=-2
    bb[3] = t[3];               // s=-1
    bb[4] = t[2];               // s= 0
    bb[5] = pk2(f2hi, f4lo);    // s= 1
    bb[6] = t[1];               // s= 2
    bb[7] = pk2(f0hi, f2lo);    // s= 3
    bb[8] = t[0];               // s= 4
    if (p <= 4) {               // voxel d0:   u = 4-p
        #pragma unroll
        for (int v = 0; v < 9; ++v) fma2(acc[0][4 - p][v], A0, bb[v]);
    }
    if (p >= 1) {               // voxel d0+1: u = 5-p
        #pragma unroll
        for (int v = 0; v < 9; ++v) fma2(acc[1][5 - p][v], A1, bb[v]);
    }
}

// Per-buffer smem layout (floats), 6 buffers (BUF = 3968 floats = 15872 B):
//   x2: 6 planes * (8 rows * 72 cols); smem col = global_w + 4 (halo cols 2,3,68,69)
//   x1 at +3456: 2 planes * (4 rows * 64 cols)
extern __shared__ float sm[];

__global__ void __launch_bounds__(128, 2)
cv3d_kernel(const float* __restrict__ x1, const float* __restrict__ x2,
            float* __restrict__ out)
{
    const int tid = threadIdx.x;
    const int hl  = tid >> 5;           // 0..3: h row (warp = one row)
    const int w   = (tid & 31) * 2;     // even w; thread owns (w, w+1)
    const int h0  = blockIdx.x * 4;
    const int d0  = blockIdx.y * 2;
    const int b   = blockIdx.z;

    const float* x1b = x1 + (size_t)b * 8388608;
    const float* x2b = x2 + (size_t)b * 8388608;
    const uint32_t smb = (uint32_t)__cvta_generic_to_shared(sm);

    // ---- compact cp.async geometry. x2 chunk q = tid + 128k (k=0..5):
    //      plane = k, row = tid>>4, cw = tid&15. x1 chunk: k=6.
    const int crow = tid >> 4, ccw = tid & 15;
    const int ghl  = h0 - 2 + crow;
    const bool ghok = ((unsigned)ghl < 64u);
    const float* srow = x2b + (size_t)(ghok ? ghl : 0) * 64 + ccw * 4;
    const uint32_t cdst0 = smb + (uint32_t)(crow * 72 + 4 + ccw * 4) * 4u;
    int gdo[6]; unsigned vmask = 0;
    #pragma unroll
    for (int k = 0; k < 6; ++k) {
        int gd = d0 - 2 + k;
        if (ghok && (unsigned)gd < 32u) vmask |= (16u << (k * 5));  // field=16 or 0
        int gdc = gd < 0 ? 0 : (gd > 31 ? 31 : gd);
        gdo[k] = gdc * 4096;
    }
    const int xa = tid >> 6, xrow = (tid >> 4) & 3, xcw = tid & 15;
    const float* xsrc = x1b + (size_t)(d0 + xa) * 4096
                            + (size_t)(h0 + xrow) * 64 + xcw * 4;
    const uint32_t xdst = smb + (uint32_t)(3456 + xa * 256 + xrow * 64 + xcw * 4) * 4u;

// fetch ONE channel into buffer BUF (no commit)
#define XF1(CC, BUF) do {                                                        \
    const uint32_t _o = (uint32_t)(BUF) * 15872u;                                \
    const size_t _c = (size_t)(CC) * 131072;                                     \
    _Pragma("unroll")                                                            \
    for (int _k = 0; _k < 6; ++_k)                                               \
        cp16(cdst0 + (uint32_t)_k * 2304u + _o, srow + _c + gdo[_k],             \
             (int)((vmask >> (_k * 5)) & 31u));                                  \
    cp16(xdst + _o, xsrc + _c, 16);                                              \
} while (0)

    // ---- prologue: pairs (0,1) -> bufs 0,1 and (2,3) -> bufs 2,3 ----
    XF1(0, 0); XF1(1, 1);
    asm volatile("cp.async.commit_group;");
    XF1(2, 2); XF1(3, 3);
    asm volatile("cp.async.commit_group;");

    // ---- zero W-halo columns of all 6 buffers (image edge => always 0) ----
    for (int q = tid; q < 288; q += 128) {
        int buf = q / 48, r = q % 48, pl = r >> 3, row = r & 7;
        float* hp = sm + buf * 3968 + pl * 576 + row * 72;
        hp[2] = 0.f; hp[3] = 0.f; hp[68] = 0.f; hp[69] = 0.f;
    }

    // ---- zero the 80 never-written output channels (23..102) for this tile ----
    {
        float* zb = out + (size_t)b * 16384000 + (size_t)23 * 131072
                        + (size_t)d0 * 4096 + (size_t)h0 * 64;
        int dd = (tid >> 6) & 1, row = (tid >> 4) & 3, cw = tid & 15;
        float* base = zb + dd * 4096 + row * 64 + cw * 4;
        const float4 z = make_float4(0.f, 0.f, 0.f, 0.f);
        #pragma unroll 4
        for (int ch = 0; ch < 80; ++ch)
            *reinterpret_cast<float4*>(base + (size_t)ch * 131072) = z;
    }

    // ---- accumulators: [d-index][dsh+2][s+4], f32x2 lanes = (w, w+1) ----
    ull acc[2][5][9];
    #pragma unroll
    for (int a = 0; a < 2; ++a)
        #pragma unroll
        for (int u = 0; u < 5; ++u)
            #pragma unroll
            for (int v = 0; v < 9; ++v) acc[a][u][v] = 0ull;

    int cb = 0;   // buffer of first channel of current pair (0,2,4 cycle)
    int pb = 4;   // buffer of first channel of pair being prefetched
    const bool oddw = (hl & 1) != 0;

    #pragma unroll 1
    for (int i = 0; i < 32; ++i) {
        if (i < 31) asm volatile("cp.async.wait_group 1;");
        else        asm volatile("cp.async.wait_group 0;");
        __syncthreads();

        if (i < 30) {
            XF1(2 * i + 4, pb); XF1(2 * i + 5, pb + 1);
            asm volatile("cp.async.commit_group;");
        }

        // Phase decorrelation: odd warps process the pair in swapped order.
        // (Only changes FP summation order inside each accumulator.)
        const float* baseF = sm + (cb + (oddw ? 1 : 0)) * 3968;  // first channel
        const float* baseS = sm + (cb + (oddw ? 0 : 1)) * 3968;  // second channel
        const float* xwA = baseF + hl * 72 + (w + 4);
        const float* xwB = baseS + hl * 72 + (w + 4);
        const float* axA = baseF + 3456 + hl * 64 + w;
        const float* axB = baseS + 3456 + hl * 64 + w;
        const ull A0  = LD64(axA), A1  = LD64(axA + 256);
        const ull A0b = LD64(axB), A1b = LD64(axB + 256);

        // ---- continuous 12-plane software pipeline across the pair ----
        ull bufA[7], bufB[7];
        loadp(bufA, xwA);                       // c1.p0
        loadp(bufB, xwA + 576);                 // c1.p1
        planefma(bufA, 0, A0, A1, acc);
        loadp(bufA, xwA + 2 * 576);             // c1.p2
        planefma(bufB, 1, A0, A1, acc);
        loadp(bufB, xwA + 3 * 576);             // c1.p3
        planefma(bufA, 2, A0, A1, acc);
        loadp(bufA, xwA + 4 * 576);             // c1.p4
        planefma(bufB, 3, A0, A1, acc);
        loadp(bufB, xwA + 5 * 576);             // c1.p5
        planefma(bufA, 4, A0, A1, acc);
        loadp(bufA, xwB);                       // c2.p0
        planefma(bufB, 5, A0, A1, acc);
        loadp(bufB, xwB + 576);                 // c2.p1
        planefma(bufA, 0, A0b, A1b, acc);
        loadp(bufA, xwB + 2 * 576);             // c2.p2
        planefma(bufB, 1, A0b, A1b, acc);
        loadp(bufB, xwB + 3 * 576);             // c2.p3
        planefma(bufA, 2, A0b, A1b, acc);
        loadp(bufA, xwB + 4 * 576);             // c2.p4
        planefma(bufB, 3, A0b, A1b, acc);
        loadp(bufB, xwB + 5 * 576);             // c2.p5
        planefma(bufA, 4, A0b, A1b, acc);
        planefma(bufB, 5, A0b, A1b, acc);

        cb += 2; if (cb >= 6) cb = 0;
        pb += 2; if (pb >= 6) pb = 0;
    }

    // ---- epilogue: scale by 1/125 and store ----
    const uint32_t invb = __float_as_uint(1.0f / 125.0f);
    const ull invv = pk2(invb, invb);
    float* ob = out + (size_t)b * 16384000 + (size_t)d0 * 4096
                    + (size_t)(h0 + hl) * 64 + w;
    #pragma unroll
    for (int a = 0; a < 2; ++a)
        #pragma unroll
        for (int u = 0; u < 5; ++u)
            #pragma unroll
            for (int v = 0; v < 9; ++v) {
                int ch = (5 * (v - 4) + (u - 2)) % 125;
                if (ch < 0) ch += 125;
                ull r = mul2(acc[a][u][v], invv);
                *reinterpret_cast<ull*>(ob + (size_t)ch * 131072 + a * 4096) = r;
            }
}

extern "C" void kernel_launch(void* const* d_in, const int* in_sizes, int n_in,
                              void* d_out, int out_size) {
    const float* x1 = (const float*)d_in[0];
    const float* x2 = (const float*)d_in[1];
    float* out = (float*)d_out;
    cudaFuncSetAttribute(cv3d_kernel,
                         cudaFuncAttributeMaxDynamicSharedMemorySize, 95232);
    cv3d_kernel<<<dim3(16, 16, 2), 128, 95232>>>(x1, x2, out);
}

// round 14
// speedup vs baseline: 1.0451x; 1.0451x over previous
#include <cuda_runtime.h>
#include <cstdint>

// CostVolumeLayer3D, B=2 C=64 D=32 H=64 W=64, R=2.
// out[b, ch(s,dsh), d, h, w] = (1/125) * sum_c x1[b,c,d,h,w] * x2[b,c,d-dsh,h-i_s,w-j_s]
//   s in [-4,4], dsh in [-2,2], (i_s,j_s) = (min(2,s+2), max(-2,s-2)),
//   ch = (5s+dsh) mod 125. Channels 23..102 are identically zero.
// 128-thr CTA (4 h-rows), thread = w-pair x d-pair, 90 f32x2 accumulators.
// 6-buffer cp.async pipeline, one barrier per channel PAIR, continuous 12-plane
// LDS/FMA pipeline. Crossbar diet: f0/f4 row neighbors come from warp shuffles
// of f2 (lane 0/31 patch via one predicated LDS from the smem halo) -> 5 LDS.64
// per plane instead of 7 (-27% crossbar bytes).

typedef unsigned long long ull;
#define LD64(p) (*reinterpret_cast<const ull*>(p))

static __device__ __forceinline__ void cp16(uint32_t dst, const float* src, int vsz) {
    asm volatile("cp.async.cg.shared.global [%0], [%1], 16, %2;"
                 :: "r"(dst), "l"(src), "r"(vsz));
}
static __device__ __forceinline__ ull pk2(uint32_t lo, uint32_t hi) {
    ull r; asm("mov.b64 %0, {%1,%2};" : "=l"(r) : "r"(lo), "r"(hi)); return r;
}
static __device__ __forceinline__ void unpk(uint32_t& lo, uint32_t& hi, ull v) {
    asm("mov.b64 {%0,%1}, %2;" : "=r"(lo), "=r"(hi) : "l"(v));
}
static __device__ __forceinline__ void fma2(ull& acc, ull a, ull b) {
    asm("fma.rn.f32x2 %0, %1, %2, %0;" : "+l"(acc) : "l"(a), "l"(b));
}
static __device__ __forceinline__ ull mul2(ull a, ull b) {
    ull r; asm("mul.rn.f32x2 %0, %1, %2;" : "=l"(r) : "l"(a), "l"(b)); return r;
}

// 5 LDS.64 per plane (pp = row gh-2, col w):
//   t0 = f2 (row gh-2, cols w,w+1); t1..t4 = column arm (cols w+2,w+3, rows gh-1..gh+2)
static __device__ __forceinline__ void loadp(ull t[5], const float* pp) {
    t[0] = LD64(pp);
    t[1] = LD64(pp + 74);
    t[2] = LD64(pp + 146);
    t[3] = LD64(pp + 218);
    t[4] = LD64(pp + 290);
}

// f0/f4 from neighbor lanes' f2; warp-edge lanes patch from the smem halo.
static __device__ __forceinline__ void planefma(
    const ull t[5], const float* pp, int p, int lane,
    ull A0, ull A1, ull acc[2][5][9])
{
    const ull f2 = t[0];
    ull f0 = __shfl_up_sync(0xffffffffu, f2, 1);
    ull f4 = __shfl_down_sync(0xffffffffu, f2, 1);
    if (lane == 0)  f0 = LD64(pp - 2);   // cols w-2,w-1 = smem halo (zeros)
    if (lane == 31) f4 = LD64(pp + 2);   // cols w+2,w+3 = smem halo (zeros)
    uint32_t f0lo, f0hi, f2lo, f2hi, f4lo, f4hi;
    unpk(f0lo, f0hi, f0); unpk(f2lo, f2hi, f2); unpk(f4lo, f4hi, f4);
    ull bb[9];
    bb[0] = t[4];               // s=-4
    bb[1] = t[3];               // s=-3
    bb[2] = t[2];               // s=-2
    bb[3] = t[1];               // s=-1
    bb[4] = f4;                 // s= 0
    bb[5] = pk2(f2hi, f4lo);    // s= 1
    bb[6] = f2;                 // s= 2
    bb[7] = pk2(f0hi, f2lo);    // s= 3
    bb[8] = f0;                 // s= 4
    if (p <= 4) {               // voxel d0:   u = 4-p
        #pragma unroll
        for (int v = 0; v < 9; ++v) fma2(acc[0][4 - p][v], A0, bb[v]);
    }
    if (p >= 1) {               // voxel d0+1: u = 5-p
        #pragma unroll
        for (int v = 0; v < 9; ++v) fma2(acc[1][5 - p][v], A1, bb[v]);
    }
}

// Per-buffer smem layout (floats), 6 buffers (BUF = 3968 floats = 15872 B):
//   x2: 6 planes * (8 rows * 72 cols); smem col = global_w + 4 (halo cols 2,3,68,69)
//   x1 at +3456: 2 planes * (4 rows * 64 cols)
extern __shared__ float sm[];

__global__ void __launch_bounds__(128, 2)
cv3d_kernel(const float* __restrict__ x1, const float* __restrict__ x2,
            float* __restrict__ out)
{
    const int tid  = threadIdx.x;
    const int hl   = tid >> 5;          // 0..3: h row (warp = one row)
    const int lane = tid & 31;
    const int w    = lane * 2;          // even w; thread owns (w, w+1)
    const int h0   = blockIdx.x * 4;
    const int d0   = blockIdx.y * 2;
    const int b    = blockIdx.z;

    const float* x1b = x1 + (size_t)b * 8388608;
    const float* x2b = x2 + (size_t)b * 8388608;
    const uint32_t smb = (uint32_t)__cvta_generic_to_shared(sm);

    // ---- compact cp.async geometry. x2 chunk q = tid + 128k (k=0..5):
    //      plane = k, row = tid>>4, cw = tid&15. x1 chunk: k=6.
    const int crow = tid >> 4, ccw = tid & 15;
    const int ghl  = h0 - 2 + crow;
    const bool ghok = ((unsigned)ghl < 64u);
    const float* srow = x2b + (size_t)(ghok ? ghl : 0) * 64 + ccw * 4;
    const uint32_t cdst0 = smb + (uint32_t)(crow * 72 + 4 + ccw * 4) * 4u;
    int gdo[6]; unsigned vmask = 0;
    #pragma unroll
    for (int k = 0; k < 6; ++k) {
        int gd = d0 - 2 + k;
        if (ghok && (unsigned)gd < 32u) vmask |= (16u << (k * 5));  // field=16 or 0
        int gdc = gd < 0 ? 0 : (gd > 31 ? 31 : gd);
        gdo[k] = gdc * 4096;
    }
    const int xa = tid >> 6, xrow = (tid >> 4) & 3, xcw = tid & 15;
    const float* xsrc = x1b + (size_t)(d0 + xa) * 4096
                            + (size_t)(h0 + xrow) * 64 + xcw * 4;
    const uint32_t xdst = smb + (uint32_t)(3456 + xa * 256 + xrow * 64 + xcw * 4) * 4u;

// fetch ONE channel into buffer BUF (no commit)
#define XF1(CC, BUF) do {                                                        \
    const uint32_t _o = (uint32_t)(BUF) * 15872u;                                \
    const size_t _c = (size_t)(CC) * 131072;                                     \
    _Pragma("unroll")                                                            \
    for (int _k = 0; _k < 6; ++_k)                                               \
        cp16(cdst0 + (uint32_t)_k * 2304u + _o, srow + _c + gdo[_k],             \
             (int)((vmask >> (_k * 5)) & 31u));                                  \
    cp16(xdst + _o, xsrc + _c, 16);                                              \
} while (0)

    // ---- prologue: pairs (0,1) -> bufs 0,1 and (2,3) -> bufs 2,3 ----
    XF1(0, 0); XF1(1, 1);
    asm volatile("cp.async.commit_group;");
    XF1(2, 2); XF1(3, 3);
    asm volatile("cp.async.commit_group;");

    // ---- zero W-halo columns of all 6 buffers (image edge => always 0) ----
    for (int q = tid; q < 288; q += 128) {
        int buf = q / 48, r = q % 48, pl = r >> 3, row = r & 7;
        float* hp = sm + buf * 3968 + pl * 576 + row * 72;
        hp[2] = 0.f; hp[3] = 0.f; hp[68] = 0.f; hp[69] = 0.f;
    }

    // ---- zero the 80 never-written output channels (23..102) for this tile ----
    {
        float* zb = out + (size_t)b * 16384000 + (size_t)23 * 131072
                        + (size_t)d0 * 4096 + (size_t)h0 * 64;
        int dd = (tid >> 6) & 1, row = (tid >> 4) & 3, cw = tid & 15;
        float* base = zb + dd * 4096 + row * 64 + cw * 4;
        const float4 z = make_float4(0.f, 0.f, 0.f, 0.f);
        #pragma unroll 4
        for (int ch = 0; ch < 80; ++ch)
            *reinterpret_cast<float4*>(base + (size_t)ch * 131072) = z;
    }

    // ---- accumulators: [d-index][dsh+2][s+4], f32x2 lanes = (w, w+1) ----
    ull acc[2][5][9];
    #pragma unroll
    for (int a = 0; a < 2; ++a)
        #pragma unroll
        for (int u = 0; u < 5; ++u)
            #pragma unroll
            for (int v = 0; v < 9; ++v) acc[a][u][v] = 0ull;

    int cb = 0;   // buffer of first channel of current pair (0,2,4 cycle)
    int pb = 4;   // buffer of first channel of pair being prefetched

    #pragma unroll 1
    for (int i = 0; i < 32; ++i) {
        if (i < 31) asm volatile("cp.async.wait_group 1;");
        else        asm volatile("cp.async.wait_group 0;");
        __syncthreads();

        if (i < 30) {
            XF1(2 * i + 4, pb); XF1(2 * i + 5, pb + 1);
            asm volatile("cp.async.commit_group;");
        }

        const float* baseA = sm + cb * 3968;
        const float* baseB = baseA + 3968;
        const float* xwA = baseA + hl * 72 + (w + 4);   // channel 2i
        const float* xwB = baseB + hl * 72 + (w + 4);   // channel 2i+1
        const float* axA = baseA + 3456 + hl * 64 + w;
        const float* axB = baseB + 3456 + hl * 64 + w;
        const ull A0  = LD64(axA), A1  = LD64(axA + 256);
        const ull A0b = LD64(axB), A1b = LD64(axB + 256);

        // ---- continuous 12-plane software pipeline across the pair ----
        ull bufA[5], bufB[5];
        loadp(bufA, xwA);                       // c1.p0
        loadp(bufB, xwA + 576);                 // c1.p1
        planefma(bufA, xwA,           0, lane, A0, A1, acc);
        loadp(bufA, xwA + 2 * 576);             // c1.p2
        planefma(bufB, xwA + 576,     1, lane, A0, A1, acc);
        loadp(bufB, xwA + 3 * 576);             // c1.p3
        planefma(bufA, xwA + 2 * 576, 2, lane, A0, A1, acc);
        loadp(bufA, xwA + 4 * 576);             // c1.p4
        planefma(bufB, xwA + 3 * 576, 3, lane, A0, A1, acc);
        loadp(bufB, xwA + 5 * 576);             // c1.p5
        planefma(bufA, xwA + 4 * 576, 4, lane, A0, A1, acc);
        loadp(bufA, xwB);                       // c2.p0
        planefma(bufB, xwA + 5 * 576, 5, lane, A0, A1, acc);
        loadp(bufB, xwB + 576);                 // c2.p1
        planefma(bufA, xwB,           0, lane, A0b, A1b, acc);
        loadp(bufA, xwB + 2 * 576);             // c2.p2
        planefma(bufB, xwB + 576,     1, lane, A0b, A1b, acc);
        loadp(bufB, xwB + 3 * 576);             // c2.p3
        planefma(bufA, xwB + 2 * 576, 2, lane, A0b, A1b, acc);
        loadp(bufA, xwB + 4 * 576);             // c2.p4
        planefma(bufB, xwB + 3 * 576, 3, lane, A0b, A1b, acc);
        loadp(bufB, xwB + 5 * 576);             // c2.p5
        planefma(bufA, xwB + 4 * 576, 4, lane, A0b, A1b, acc);
        planefma(bufB, xwB + 5 * 576, 5, lane, A0b, A1b, acc);

        cb += 2; if (cb >= 6) cb = 0;
        pb += 2; if (pb >= 6) pb = 0;
    }

    // ---- epilogue: scale by 1/125 and store ----
    const uint32_t invb = __float_as_uint(1.0f / 125.0f);
    const ull invv = pk2(invb, invb);
    float* ob = out + (size_t)b * 16384000 + (size_t)d0 * 4096
                    + (size_t)(h0 + hl) * 64 + w;
    #pragma unroll
    for (int a = 0; a < 2; ++a)
        #pragma unroll
        for (int u = 0; u < 5; ++u)
            #pragma unroll
            for (int v = 0; v < 9; ++v) {
                int ch = (5 * (v - 4) + (u - 2)) % 125;
                if (ch < 0) ch += 125;
                ull r = mul2(acc[a][u][v], invv);
                *reinterpret_cast<ull*>(ob + (size_t)ch * 131072 + a * 4096) = r;
            }
}

extern "C" void kernel_launch(void* const* d_in, const int* in_sizes, int n_in,
                              void* d_out, int out_size) {
    const float* x1 = (const float*)d_in[0];
    const float* x2 = (const float*)d_in[1];
    float* out = (float*)d_out;
    cudaFuncSetAttribute(cv3d_kernel,
                         cudaFuncAttributeMaxDynamicSharedMemorySize, 95232);
    cv3d_kernel<<<dim3(16, 16, 2), 128, 95232>>>(x1, x2, out);
}

// round 15
// speedup vs baseline: 1.1931x; 1.1416x over previous
#include <cuda_runtime.h>
#include <cstdint>

// CostVolumeLayer3D, B=2 C=64 D=32 H=64 W=64, R=2.
// out[b, ch(s,dsh), d, h, w] = (1/125) * sum_c x1[b,c,d,h,w] * x2[b,c,d-dsh,h-i_s,w-j_s]
//   s in [-4,4], dsh in [-2,2], (i_s,j_s) = (min(2,s+2), max(-2,s-2)),
//   ch = (5s+dsh) mod 125. Channels 23..102 are identically zero.
// 128-thr CTA (4 h-rows), thread = w-pair x d-pair, 90 f32x2 accumulators.
// 6-buffer cp.async pipeline, one barrier per channel PAIR, continuous 12-plane
// LDS/FMA pipeline. NEW: cp.async (LDGSTS, rt=8) issue moved from the body HEAD
// to the FMA-heavy middle so it no longer starves LDS issue while the plane
// pipeline is filling; second channel's x1 loads likewise deferred.

typedef unsigned long long ull;
#define LD64(p) (*reinterpret_cast<const ull*>(p))

static __device__ __forceinline__ void cp16(uint32_t dst, const float* src, int vsz) {
    asm volatile("cp.async.cg.shared.global [%0], [%1], 16, %2;"
                 :: "r"(dst), "l"(src), "r"(vsz));
}
static __device__ __forceinline__ ull pk2(uint32_t lo, uint32_t hi) {
    ull r; asm("mov.b64 %0, {%1,%2};" : "=l"(r) : "r"(lo), "r"(hi)); return r;
}
static __device__ __forceinline__ void unpk(uint32_t& lo, uint32_t& hi, ull v) {
    asm("mov.b64 {%0,%1}, %2;" : "=r"(lo), "=r"(hi) : "l"(v));
}
static __device__ __forceinline__ void fma2(ull& acc, ull a, ull b) {
    asm("fma.rn.f32x2 %0, %1, %2, %0;" : "+l"(acc) : "l"(a), "l"(b));
}
static __device__ __forceinline__ ull mul2(ull a, ull b) {
    ull r; asm("mul.rn.f32x2 %0, %1, %2;" : "=l"(r) : "l"(a), "l"(b)); return r;
}

// Load the 7 b-values of one x2 plane from smem (pp = row gh-2, col w).
static __device__ __forceinline__ void loadp(ull t[7], const float* pp) {
    t[0] = LD64(pp - 2);    // row gh-2: cols w-2,w-1
    t[1] = LD64(pp);        //            cols w,  w+1
    t[2] = LD64(pp + 2);    //            cols w+2,w+3
    t[3] = LD64(pp + 74);   // row gh-1, cols w+2,w+3
    t[4] = LD64(pp + 146);  // row gh
    t[5] = LD64(pp + 218);  // row gh+1
    t[6] = LD64(pp + 290);  // row gh+2
}

static __device__ __forceinline__ void planefma(
    const ull t[7], int p, ull A0, ull A1, ull acc[2][5][9])
{
    uint32_t f0lo, f0hi, f2lo, f2hi, f4lo, f4hi;
    unpk(f0lo, f0hi, t[0]); unpk(f2lo, f2hi, t[1]); unpk(f4lo, f4hi, t[2]);
    ull bb[9];
    bb[0] = t[6];               // s=-4
    bb[1] = t[5];               // s=-3
    bb[2] = t[4];               // s=-2
    bb[3] = t[3];               // s=-1
    bb[4] = t[2];               // s= 0
    bb[5] = pk2(f2hi, f4lo);    // s= 1
    bb[6] = t[1];               // s= 2
    bb[7] = pk2(f0hi, f2lo);    // s= 3
    bb[8] = t[0];               // s= 4
    if (p <= 4) {               // voxel d0:   u = 4-p
        #pragma unroll
        for (int v = 0; v < 9; ++v) fma2(acc[0][4 - p][v], A0, bb[v]);
    }
    if (p >= 1) {               // voxel d0+1: u = 5-p
        #pragma unroll
        for (int v = 0; v < 9; ++v) fma2(acc[1][5 - p][v], A1, bb[v]);
    }
}

// Per-buffer smem layout (floats), 6 buffers (BUF = 3968 floats = 15872 B):
//   x2: 6 planes * (8 rows * 72 cols); smem col = global_w + 4 (halo cols 2,3,68,69)
//   x1 at +3456: 2 planes * (4 rows * 64 cols)
extern __shared__ float sm[];

__global__ void __launch_bounds__(128, 2)
cv3d_kernel(const float* __restrict__ x1, const float* __restrict__ x2,
            float* __restrict__ out)
{
    const int tid = threadIdx.x;
    const int hl  = tid >> 5;           // 0..3: h row (warp = one row)
    const int w   = (tid & 31) * 2;     // even w; thread owns (w, w+1)
    const int h0  = blockIdx.x * 4;
    const int d0  = blockIdx.y * 2;
    const int b   = blockIdx.z;

    const float* x1b = x1 + (size_t)b * 8388608;
    const float* x2b = x2 + (size_t)b * 8388608;
    const uint32_t smb = (uint32_t)__cvta_generic_to_shared(sm);

    // ---- compact cp.async geometry. x2 chunk q = tid + 128k (k=0..5):
    //      plane = k, row = tid>>4, cw = tid&15. x1 chunk: k=6.
    const int crow = tid >> 4, ccw = tid & 15;
    const int ghl  = h0 - 2 + crow;
    const bool ghok = ((unsigned)ghl < 64u);
    const float* srow = x2b + (size_t)(ghok ? ghl : 0) * 64 + ccw * 4;
    const uint32_t cdst0 = smb + (uint32_t)(crow * 72 + 4 + ccw * 4) * 4u;
    int gdo[6]; unsigned vmask = 0;
    #pragma unroll
    for (int k = 0; k < 6; ++k) {
        int gd = d0 - 2 + k;
        if (ghok && (unsigned)gd < 32u) vmask |= (16u << (k * 5));  // field=16 or 0
        int gdc = gd < 0 ? 0 : (gd > 31 ? 31 : gd);
        gdo[k] = gdc * 4096;
    }
    const int xa = tid >> 6, xrow = (tid >> 4) & 3, xcw = tid & 15;
    const float* xsrc = x1b + (size_t)(d0 + xa) * 4096
                            + (size_t)(h0 + xrow) * 64 + xcw * 4;
    const uint32_t xdst = smb + (uint32_t)(3456 + xa * 256 + xrow * 64 + xcw * 4) * 4u;

// fetch ONE channel into buffer BUF (no commit)
#define XF1(CC, BUF) do {                                                        \
    const uint32_t _o = (uint32_t)(BUF) * 15872u;                                \
    const size_t _c = (size_t)(CC) * 131072;                                     \
    _Pragma("unroll")                                                            \
    for (int _k = 0; _k < 6; ++_k)                                               \
        cp16(cdst0 + (uint32_t)_k * 2304u + _o, srow + _c + gdo[_k],             \
             (int)((vmask >> (_k * 5)) & 31u));                                  \
    cp16(xdst + _o, xsrc + _c, 16);                                              \
} while (0)

    // ---- prologue: pairs (0,1) -> bufs 0,1 and (2,3) -> bufs 2,3 ----
    XF1(0, 0); XF1(1, 1);
    asm volatile("cp.async.commit_group;");
    XF1(2, 2); XF1(3, 3);
    asm volatile("cp.async.commit_group;");

    // ---- zero W-halo columns of all 6 buffers (image edge => always 0) ----
    for (int q = tid; q < 288; q += 128) {
        int buf = q / 48, r = q % 48, pl = r >> 3, row = r & 7;
        float* hp = sm + buf * 3968 + pl * 576 + row * 72;
        hp[2] = 0.f; hp[3] = 0.f; hp[68] = 0.f; hp[69] = 0.f;
    }

    // ---- zero the 80 never-written output channels (23..102) for this tile ----
    {
        float* zb = out + (size_t)b * 16384000 + (size_t)23 * 131072
                        + (size_t)d0 * 4096 + (size_t)h0 * 64;
        int dd = (tid >> 6) & 1, row = (tid >> 4) & 3, cw = tid & 15;
        float* base = zb + dd * 4096 + row * 64 + cw * 4;
        const float4 z = make_float4(0.f, 0.f, 0.f, 0.f);
        #pragma unroll 4
        for (int ch = 0; ch < 80; ++ch)
            *reinterpret_cast<float4*>(base + (size_t)ch * 131072) = z;
    }

    // ---- accumulators: [d-index][dsh+2][s+4], f32x2 lanes = (w, w+1) ----
    ull acc[2][5][9];
    #pragma unroll
    for (int a = 0; a < 2; ++a)
        #pragma unroll
        for (int u = 0; u < 5; ++u)
            #pragma unroll
            for (int v = 0; v < 9; ++v) acc[a][u][v] = 0ull;

    int cb = 0;   // buffer of first channel of current pair (0,2,4 cycle)
    int pb = 4;   // buffer of first channel of pair being prefetched

    #pragma unroll 1
    for (int i = 0; i < 32; ++i) {
        if (i < 31) asm volatile("cp.async.wait_group 1;");
        else        asm volatile("cp.async.wait_group 0;");
        __syncthreads();

        const float* baseA = sm + cb * 3968;
        const float* baseB = baseA + 3968;
        const float* xwA = baseA + hl * 72 + (w + 4);   // channel 2i
        const float* xwB = baseB + hl * 72 + (w + 4);   // channel 2i+1
        const float* axA = baseA + 3456 + hl * 64 + w;
        const float* axB = baseB + 3456 + hl * 64 + w;

        // ---- head: fill the LDS plane pipeline FIRST (no LDGSTS in the way) ----
        ull bufA[7], bufB[7];
        loadp(bufA, xwA);                       // c1.p0
        const ull A0 = LD64(axA), A1 = LD64(axA + 256);
        loadp(bufB, xwA + 576);                 // c1.p1
        planefma(bufA, 0, A0, A1, acc);
        loadp(bufA, xwA + 2 * 576);             // c1.p2
        planefma(bufB, 1, A0, A1, acc);
        loadp(bufB, xwA + 3 * 576);             // c1.p3
        planefma(bufA, 2, A0, A1, acc);

        // ---- mid-body: first prefetch channel (overlaps FMA phase) ----
        if (i < 30) XF1(2 * i + 4, pb);

        loadp(bufA, xwA + 4 * 576);             // c1.p4
        planefma(bufB, 3, A0, A1, acc);
        loadp(bufB, xwA + 5 * 576);             // c1.p5
        planefma(bufA, 4, A0, A1, acc);
        loadp(bufA, xwB);                       // c2.p0
        const ull A0b = LD64(axB), A1b = LD64(axB + 256);
        planefma(bufB, 5, A0, A1, acc);

        // ---- mid-body: second prefetch channel + commit ----
        if (i < 30) {
            XF1(2 * i + 5, pb + 1);
            asm volatile("cp.async.commit_group;");
        }

        loadp(bufB, xwB + 576);                 // c2.p1
        planefma(bufA, 0, A0b, A1b, acc);
        loadp(bufA, xwB + 2 * 576);             // c2.p2
        planefma(bufB, 1, A0b, A1b, acc);
        loadp(bufB, xwB + 3 * 576);             // c2.p3
        planefma(bufA, 2, A0b, A1b, acc);
        loadp(bufA, xwB + 4 * 576);             // c2.p4
        planefma(bufB, 3, A0b, A1b, acc);
        loadp(bufB, xwB + 5 * 576);             // c2.p5
        planefma(bufA, 4, A0b, A1b, acc);
        planefma(bufB, 5, A0b, A1b, acc);

        cb += 2; if (cb >= 6) cb = 0;
        pb += 2; if (pb >= 6) pb = 0;
    }

    // ---- epilogue: scale by 1/125 and store ----
    const uint32_t invb = __float_as_uint(1.0f / 125.0f);
    const ull invv = pk2(invb, invb);
    float* ob = out + (size_t)b * 16384000 + (size_t)d0 * 4096
                    + (size_t)(h0 + hl) * 64 + w;
    #pragma unroll
    for (int a = 0; a < 2; ++a)
        #pragma unroll
        for (int u = 0; u < 5; ++u)
            #pragma unroll
            for (int v = 0; v < 9; ++v) {
                int ch = (5 * (v - 4) + (u - 2)) % 125;
                if (ch < 0) ch += 125;
                ull r = mul2(acc[a][u][v], invv);
                *reinterpret_cast<ull*>(ob + (size_t)ch * 131072 + a * 4096) = r;
            }
}

extern "C" void kernel_launch(void* const* d_in, const int* in_sizes, int n_in,
                              void* d_out, int out_size) {
    const float* x1 = (const float*)d_in[0];
    const float* x2 = (const float*)d_in[1];
    float* out = (float*)d_out;
    cudaFuncSetAttribute(cv3d_kernel,
                         cudaFuncAttributeMaxDynamicSharedMemorySize, 95232);
    cv3d_kernel<<<dim3(16, 16, 2), 128, 95232>>>(x1, x2, out);
}

// round 16
// speedup vs baseline: 1.3012x; 1.0906x over previous
#include <cuda_runtime.h>
#include <cstdint>

// CostVolumeLayer3D, B=2 C=64 D=32 H=64 W=64, R=2.
// out[b, ch(s,dsh), d, h, w] = (1/125) * sum_c x1[b,c,d,h,w] * x2[b,c,d-dsh,h-i_s,w-j_s]
//   s in [-4,4], dsh in [-2,2], (i_s,j_s) = (min(2,s+2), max(-2,s-2)),
//   ch = (5s+dsh) mod 125. Channels 23..102 are identically zero.
// 128-thr CTA (4 h-rows), thread = w-pair x d-pair, 90 f32x2 accumulators.
// 6-buffer cp.async pipeline, one barrier per channel PAIR, continuous 12-plane
// LDS/FMA pipeline. R14 win extended: LDGSTS issue spread as 2-op micro-clumps
// between planefma blocks (max contiguous MIO occupancy ~16 cyc), head & tail
// kept LDGSTS-free.

typedef unsigned long long ull;
#define LD64(p) (*reinterpret_cast<const ull*>(p))

static __device__ __forceinline__ void cp16(uint32_t dst, const float* src, int vsz) {
    asm volatile("cp.async.cg.shared.global [%0], [%1], 16, %2;"
                 :: "r"(dst), "l"(src), "r"(vsz));
}
static __device__ __forceinline__ ull pk2(uint32_t lo, uint32_t hi) {
    ull r; asm("mov.b64 %0, {%1,%2};" : "=l"(r) : "r"(lo), "r"(hi)); return r;
}
static __device__ __forceinline__ void unpk(uint32_t& lo, uint32_t& hi, ull v) {
    asm("mov.b64 {%0,%1}, %2;" : "=r"(lo), "=r"(hi) : "l"(v));
}
static __device__ __forceinline__ void fma2(ull& acc, ull a, ull b) {
    asm("fma.rn.f32x2 %0, %1, %2, %0;" : "+l"(acc) : "l"(a), "l"(b));
}
static __device__ __forceinline__ ull mul2(ull a, ull b) {
    ull r; asm("mul.rn.f32x2 %0, %1, %2;" : "=l"(r) : "l"(a), "l"(b)); return r;
}

// Load the 7 b-values of one x2 plane from smem (pp = row gh-2, col w).
static __device__ __forceinline__ void loadp(ull t[7], const float* pp) {
    t[0] = LD64(pp - 2);    // row gh-2: cols w-2,w-1
    t[1] = LD64(pp);        //            cols w,  w+1
    t[2] = LD64(pp + 2);    //            cols w+2,w+3
    t[3] = LD64(pp + 74);   // row gh-1, cols w+2,w+3
    t[4] = LD64(pp + 146);  // row gh
    t[5] = LD64(pp + 218);  // row gh+1
    t[6] = LD64(pp + 290);  // row gh+2
}

static __device__ __forceinline__ void planefma(
    const ull t[7], int p, ull A0, ull A1, ull acc[2][5][9])
{
    uint32_t f0lo, f0hi, f2lo, f2hi, f4lo, f4hi;
    unpk(f0lo, f0hi, t[0]); unpk(f2lo, f2hi, t[1]); unpk(f4lo, f4hi, t[2]);
    ull bb[9];
    bb[0] = t[6];               // s=-4
    bb[1] = t[5];               // s=-3
    bb[2] = t[4];               // s=-2
    bb[3] = t[3];               // s=-1
    bb[4] = t[2];               // s= 0
    bb[5] = pk2(f2hi, f4lo);    // s= 1
    bb[6] = t[1];               // s= 2
    bb[7] = pk2(f0hi, f2lo);    // s= 3
    bb[8] = t[0];               // s= 4
    if (p <= 4) {               // voxel d0:   u = 4-p
        #pragma unroll
        for (int v = 0; v < 9; ++v) fma2(acc[0][4 - p][v], A0, bb[v]);
    }
    if (p >= 1) {               // voxel d0+1: u = 5-p
        #pragma unroll
        for (int v = 0; v < 9; ++v) fma2(acc[1][5 - p][v], A1, bb[v]);
    }
}

// Per-buffer smem layout (floats), 6 buffers (BUF = 3968 floats = 15872 B):
//   x2: 6 planes * (8 rows * 72 cols); smem col = global_w + 4 (halo cols 2,3,68,69)
//   x1 at +3456: 2 planes * (4 rows * 64 cols)
extern __shared__ float sm[];

__global__ void __launch_bounds__(128, 2)
cv3d_kernel(const float* __restrict__ x1, const float* __restrict__ x2,
            float* __restrict__ out)
{
    const int tid = threadIdx.x;
    const int hl  = tid >> 5;           // 0..3: h row (warp = one row)
    const int w   = (tid & 31) * 2;     // even w; thread owns (w, w+1)
    const int h0  = blockIdx.x * 4;
    const int d0  = blockIdx.y * 2;
    const int b   = blockIdx.z;

    const float* x1b = x1 + (size_t)b * 8388608;
    const float* x2b = x2 + (size_t)b * 8388608;
    const uint32_t smb = (uint32_t)__cvta_generic_to_shared(sm);

    // ---- compact cp.async geometry. x2 chunk q = tid + 128k (k=0..5):
    //      plane = k, row = tid>>4, cw = tid&15. x1 chunk: k=6.
    const int crow = tid >> 4, ccw = tid & 15;
    const int ghl  = h0 - 2 + crow;
    const bool ghok = ((unsigned)ghl < 64u);
    const float* srow = x2b + (size_t)(ghok ? ghl : 0) * 64 + ccw * 4;
    const uint32_t cdst0 = smb + (uint32_t)(crow * 72 + 4 + ccw * 4) * 4u;
    int gdo[6]; unsigned vmask = 0;
    #pragma unroll
    for (int k = 0; k < 6; ++k) {
        int gd = d0 - 2 + k;
        if (ghok && (unsigned)gd < 32u) vmask |= (16u << (k * 5));  // field=16 or 0
        int gdc = gd < 0 ? 0 : (gd > 31 ? 31 : gd);
        gdo[k] = gdc * 4096;
    }
    const int xa = tid >> 6, xrow = (tid >> 4) & 3, xcw = tid & 15;
    const float* xsrc = x1b + (size_t)(d0 + xa) * 4096
                            + (size_t)(h0 + xrow) * 64 + xcw * 4;
    const uint32_t xdst = smb + (uint32_t)(3456 + xa * 256 + xrow * 64 + xcw * 4) * 4u;

// one x2 chunk K of channel CC into buffer BUF
#define XFK(CC, BUF, K)                                                          \
    cp16(cdst0 + (uint32_t)(K) * 2304u + (uint32_t)(BUF) * 15872u,               \
         srow + (size_t)(CC) * 131072 + gdo[(K)],                                \
         (int)((vmask >> ((K) * 5)) & 31u))
// the x1 chunk of channel CC into buffer BUF
#define XFX(CC, BUF)                                                             \
    cp16(xdst + (uint32_t)(BUF) * 15872u, xsrc + (size_t)(CC) * 131072, 16)
// fetch ONE full channel (prologue use only)
#define XF1(CC, BUF) do {                                                        \
    _Pragma("unroll")                                                            \
    for (int _k = 0; _k < 6; ++_k) { XFK(CC, BUF, _k); }                         \
    XFX(CC, BUF);                                                                \
} while (0)

    // ---- prologue: pairs (0,1) -> bufs 0,1 and (2,3) -> bufs 2,3 ----
    XF1(0, 0); XF1(1, 1);
    asm volatile("cp.async.commit_group;");
    XF1(2, 2); XF1(3, 3);
    asm volatile("cp.async.commit_group;");

    // ---- zero W-halo columns of all 6 buffers (image edge => always 0) ----
    for (int q = tid; q < 288; q += 128) {
        int buf = q / 48, r = q % 48, pl = r >> 3, row = r & 7;
        float* hp = sm + buf * 3968 + pl * 576 + row * 72;
        hp[2] = 0.f; hp[3] = 0.f; hp[68] = 0.f; hp[69] = 0.f;
    }

    // ---- zero the 80 never-written output channels (23..102) for this tile ----
    {
        float* zb = out + (size_t)b * 16384000 + (size_t)23 * 131072
                        + (size_t)d0 * 4096 + (size_t)h0 * 64;
        int dd = (tid >> 6) & 1, row = (tid >> 4) & 3, cw = tid & 15;
        float* base = zb + dd * 4096 + row * 64 + cw * 4;
        const float4 z = make_float4(0.f, 0.f, 0.f, 0.f);
        #pragma unroll 4
        for (int ch = 0; ch < 80; ++ch)
            *reinterpret_cast<float4*>(base + (size_t)ch * 131072) = z;
    }

    // ---- accumulators: [d-index][dsh+2][s+4], f32x2 lanes = (w, w+1) ----
    ull acc[2][5][9];
    #pragma unroll
    for (int a = 0; a < 2; ++a)
        #pragma unroll
        for (int u = 0; u < 5; ++u)
            #pragma unroll
            for (int v = 0; v < 9; ++v) acc[a][u][v] = 0ull;

    int cb = 0;   // buffer of first channel of current pair (0,2,4 cycle)
    int pb = 4;   // buffer of first channel of pair being prefetched

    #pragma unroll 1
    for (int i = 0; i < 32; ++i) {
        if (i < 31) asm volatile("cp.async.wait_group 1;");
        else        asm volatile("cp.async.wait_group 0;");
        __syncthreads();

        const float* baseA = sm + cb * 3968;
        const float* baseB = baseA + 3968;
        const float* xwA = baseA + hl * 72 + (w + 4);   // channel 2i
        const float* xwB = baseB + hl * 72 + (w + 4);   // channel 2i+1
        const float* axA = baseA + 3456 + hl * 64 + w;
        const float* axB = baseB + 3456 + hl * 64 + w;
        const bool pf = (i < 30);
        const int cA = 2 * i + 4, cB = 2 * i + 5;

        // ---- head: fill the LDS plane pipeline (LDGSTS-free) ----
        ull bufA[7], bufB[7];
        loadp(bufA, xwA);                       // c1.p0
        const ull A0 = LD64(axA), A1 = LD64(axA + 256);
        loadp(bufB, xwA + 576);                 // c1.p1
        planefma(bufA, 0, A0, A1, acc);
        loadp(bufA, xwA + 2 * 576);             // c1.p2
        planefma(bufB, 1, A0, A1, acc);
        loadp(bufB, xwA + 3 * 576);             // c1.p3
        planefma(bufA, 2, A0, A1, acc);

        // ---- FMA-phase micro-clumps: 2 LDGSTS between plane blocks ----
        if (pf) { XFK(cA, pb, 0); XFK(cA, pb, 1); }
        loadp(bufA, xwA + 4 * 576);             // c1.p4
        planefma(bufB, 3, A0, A1, acc);
        if (pf) { XFK(cA, pb, 2); XFK(cA, pb, 3); }
        loadp(bufB, xwA + 5 * 576);             // c1.p5
        planefma(bufA, 4, A0, A1, acc);
        if (pf) { XFK(cA, pb, 4); XFK(cA, pb, 5); }
        loadp(bufA, xwB);                       // c2.p0
        const ull A0b = LD64(axB), A1b = LD64(axB + 256);
        planefma(bufB, 5, A0, A1, acc);
        if (pf) { XFX(cA, pb); XFK(cB, pb + 1, 0); }
        loadp(bufB, xwB + 576);                 // c2.p1
        planefma(bufA, 0, A0b, A1b, acc);
        if (pf) { XFK(cB, pb + 1, 1); XFK(cB, pb + 1, 2); }
        loadp(bufA, xwB + 2 * 576);             // c2.p2
        planefma(bufB, 1, A0b, A1b, acc);
        if (pf) { XFK(cB, pb + 1, 3); XFK(cB, pb + 1, 4); }
        loadp(bufB, xwB + 3 * 576);             // c2.p3
        planefma(bufA, 2, A0b, A1b, acc);
        if (pf) {
            XFK(cB, pb + 1, 5); XFX(cB, pb + 1);
            asm volatile("cp.async.commit_group;");
        }

        // ---- tail: LDGSTS-free so next head starts with empty MIO queue ----
        loadp(bufA, xwB + 4 * 576);             // c2.p4
        planefma(bufB, 3, A0b, A1b, acc);
        loadp(bufB, xwB + 5 * 576);             // c2.p5
        planefma(bufA, 4, A0b, A1b, acc);
        planefma(bufB, 5, A0b, A1b, acc);

        cb += 2; if (cb >= 6) cb = 0;
        pb += 2; if (pb >= 6) pb = 0;
    }

    // ---- epilogue: scale by 1/125 and store ----
    const uint32_t invb = __float_as_uint(1.0f / 125.0f);
    const ull invv = pk2(invb, invb);
    float* ob = out + (size_t)b * 16384000 + (size_t)d0 * 4096
                    + (size_t)(h0 + hl) * 64 + w;
    #pragma unroll
    for (int a = 0; a < 2; ++a)
        #pragma unroll
        for (int u = 0; u < 5; ++u)
            #pragma unroll
            for (int v = 0; v < 9; ++v) {
                int ch = (5 * (v - 4) + (u - 2)) % 125;
                if (ch < 0) ch += 125;
                ull r = mul2(acc[a][u][v], invv);
                *reinterpret_cast<ull*>(ob + (size_t)ch * 131072 + a * 4096) = r;
            }
}

extern "C" void kernel_launch(void* const* d_in, const int* in_sizes, int n_in,
                              void* d_out, int out_size) {
    const float* x1 = (const float*)d_in[0];
    const float* x2 = (const float*)d_in[1];
    float* out = (float*)d_out;
    cudaFuncSetAttribute(cv3d_kernel,
                         cudaFuncAttributeMaxDynamicSharedMemorySize, 95232);
    cv3d_kernel<<<dim3(16, 16, 2), 128, 95232>>>(x1, x2, out);
}